// round 2
// baseline (speedup 1.0000x reference)
#include <cuda_runtime.h>
#include <cstddef>

// ForwardSim: B=32768 rows, T=50 steps, MLP 73->128->128->1 with per-row scalar
// carry. Persistent 64-row CTA tiles; W2 in smem; time-invariant proj@W1[:64]
// precomputed into registers. R2: hot GEMM converted to packed fma.rn.f32x2
// (column-paired accumulators) to halve FMA instruction count (FFMA-3reg is
// rt=2; f32x2 does 2 MACs per slot).

namespace {
constexpr int kB = 32768;
constexpr int kT = 50;
constexpr int kH = 128;
constexpr int kM = 64;        // batch rows per CTA
constexpr int kThreads = 256; // 16x16 thread grid, 4 rows x 8 cols per thread
constexpr int kPitch = 132;   // smem pitch (floats) for 128-wide tiles

constexpr int OFF_W2  = 0;                     // 128 x 132 (phase1: proj tile, pitch 65)
constexpr int OFF_H1  = OFF_W2 + 128 * kPitch; // 64 x 132  (phase1: W1proj)
constexpr int OFF_W1E = OFF_H1 + kM * kPitch;  // 9 x 128
constexpr int OFF_ENV = OFF_W1E + 9 * kH;      // 64 x 12
constexpr int OFF_ACT = OFF_ENV + kM * 12;     // 64
constexpr int OFF_SC  = OFF_ACT + kM;          // 16
constexpr int SMEM_FLOATS = OFF_SC + 16;
} // namespace

using ull = unsigned long long;

__device__ __forceinline__ ull pack_dup(float v) {
    ull r;
    asm("mov.b64 %0, {%1, %1};" : "=l"(r) : "f"(v));
    return r;
}
__device__ __forceinline__ ull pack2(float lo, float hi) {
    ull r;
    asm("mov.b64 %0, {%1, %2};" : "=l"(r) : "f"(lo), "f"(hi));
    return r;
}
__device__ __forceinline__ void unpack2(ull v, float& lo, float& hi) {
    asm("mov.b64 {%0, %1}, %2;" : "=f"(lo), "=f"(hi) : "l"(v));
}
__device__ __forceinline__ ull fma2(ull a, ull b, ull c) {
    ull d;
    asm("fma.rn.f32x2 %0, %1, %2, %3;" : "=l"(d) : "l"(a), "l"(b), "l"(c));
    return d;
}

__global__ void __launch_bounds__(kThreads, 2)
fsim_kernel(const float* __restrict__ proj, const float* __restrict__ idm,
            const float* __restrict__ merg, const float* __restrict__ W1,
            const float* __restrict__ b1,   const float* __restrict__ W2,
            const float* __restrict__ b2,   const float* __restrict__ W3,
            const float* __restrict__ b3,   const float* __restrict__ smean,
            const float* __restrict__ svar, float* __restrict__ out)
{
    extern __shared__ float smem[];
    float* W2s  = smem + OFF_W2;
    float* h1s  = smem + OFF_H1;
    float* W1e  = smem + OFF_W1E;
    float* envs = smem + OFF_ENV;
    float* acts = smem + OFF_ACT;
    float* scal = smem + OFF_SC;

    const int tid = threadIdx.x;
    const int tx  = tid & 15;
    const int ty  = tid >> 4;
    const int c0  = tx * 8;
    const int r0  = ty * 4;
    const int rowBase = blockIdx.x * kM;

    // ================= phase 1: projAcc = proj_belief @ W1[:64] + b1 ========
    for (int i = tid; i < 64 * kH; i += kThreads)
        h1s[(i >> 7) * kPitch + (i & 127)] = W1[i];
    for (int i = tid; i < kM * 64; i += kThreads) {
        int m = i >> 6, k = i & 63;
        W2s[m * 65 + k] = proj[(size_t)(rowBase + m) * 64 + k];
    }
    __syncthreads();

    ull projAcc[4][4];
    #pragma unroll
    for (int j = 0; j < 4; j++) {
        ull bv = pack2(__ldg(&b1[c0 + 2 * j]), __ldg(&b1[c0 + 2 * j + 1]));
        #pragma unroll
        for (int r = 0; r < 4; r++) projAcc[r][j] = bv;
    }
    #pragma unroll 2
    for (int k = 0; k < 64; k++) {
        ull av2[4];
        #pragma unroll
        for (int r = 0; r < 4; r++) av2[r] = pack_dup(W2s[(r0 + r) * 65 + k]);
        ulonglong2 wA = *(const ulonglong2*)&h1s[k * kPitch + c0];
        ulonglong2 wB = *(const ulonglong2*)&h1s[k * kPitch + c0 + 4];
        #pragma unroll
        for (int r = 0; r < 4; r++) {
            projAcc[r][0] = fma2(av2[r], wA.x, projAcc[r][0]);
            projAcc[r][1] = fma2(av2[r], wA.y, projAcc[r][1]);
            projAcc[r][2] = fma2(av2[r], wB.x, projAcc[r][2]);
            projAcc[r][3] = fma2(av2[r], wB.y, projAcc[r][3]);
        }
    }
    __syncthreads();

    // ================= load persistent weights ==============================
    for (int i = tid; i < kH * kH; i += kThreads)
        W2s[(i >> 7) * kPitch + (i & 127)] = W2[i];
    for (int i = tid; i < 9 * kH; i += kThreads)
        W1e[i] = W1[64 * kH + i];
    if (tid < 6) {
        scal[tid]     = smean[tid];
        scal[8 + tid] = rsqrtf(svar[tid]);
    }
    ull b2p[4];
    float w3r[8];
    #pragma unroll
    for (int j = 0; j < 4; j++)
        b2p[j] = pack2(__ldg(&b2[c0 + 2 * j]), __ldg(&b2[c0 + 2 * j + 1]));
    #pragma unroll
    for (int c = 0; c < 8; c++) w3r[c] = __ldg(&W3[c0 + c]);
    const float b3v = __ldg(&b3[0]);

    float ego_v = 0.f, ego_x = 0.f;   // live only in threads tid < 64
    __syncthreads();

    // ================= timestep loop ========================================
    for (int t = 0; t < kT; t++) {
        // ---- per-row carry update + env features ----
        if (tid < kM) {
            const int row = rowBase + tid;
            const float* sp = idm + (size_t)row * (kT * 12) + t * 12;
            float4 a0 = *(const float4*)sp;
            float4 a1 = *(const float4*)(sp + 4);
            float s11 = sp[11];
            if (t == 0) {
                ego_v = a0.x;
                ego_x = a0.w;
            } else {
                float a = acts[tid];
                ego_v = fmaf(a, 0.1f, ego_v);
                ego_x = ego_x + ego_v * 0.1f + a * 0.005f;
            }
            float ev[6];
            ev[0] = ego_v;
            ev[1] = a0.y;
            ev[2] = ego_v - a0.y;
            ev[3] = a1.x - ego_x;
            ev[4] = (ego_v - a0.z) * s11;
            ev[5] = (a1.y - ego_x) * s11 + (1.0f - s11) * 100.0f;
            #pragma unroll
            for (int k = 0; k < 6; k++)
                envs[tid * 12 + k] = (ev[k] - scal[k]) * scal[8 + k];
            const float* mp = merg + (size_t)row * (kT * 3) + t * 3;
            envs[tid * 12 + 6] = mp[0];
            envs[tid * 12 + 7] = mp[1];
            envs[tid * 12 + 8] = mp[2];
        }
        __syncthreads();

        // ---- h1 = relu(projAcc + [env,mc] @ W1[64:73]) -> smem ----
        {
            ull hv[4][4];
            #pragma unroll
            for (int r = 0; r < 4; r++)
                #pragma unroll
                for (int j = 0; j < 4; j++) hv[r][j] = projAcc[r][j];
            #pragma unroll
            for (int k = 0; k < 9; k++) {
                ull ev2[4];
                #pragma unroll
                for (int r = 0; r < 4; r++)
                    ev2[r] = pack_dup(envs[(r0 + r) * 12 + k]);
                ulonglong2 wA = *(const ulonglong2*)&W1e[k * kH + c0];
                ulonglong2 wB = *(const ulonglong2*)&W1e[k * kH + c0 + 4];
                #pragma unroll
                for (int r = 0; r < 4; r++) {
                    hv[r][0] = fma2(ev2[r], wA.x, hv[r][0]);
                    hv[r][1] = fma2(ev2[r], wA.y, hv[r][1]);
                    hv[r][2] = fma2(ev2[r], wB.x, hv[r][2]);
                    hv[r][3] = fma2(ev2[r], wB.y, hv[r][3]);
                }
            }
            #pragma unroll
            for (int r = 0; r < 4; r++) {
                float v[8];
                #pragma unroll
                for (int j = 0; j < 4; j++)
                    unpack2(hv[r][j], v[2 * j], v[2 * j + 1]);
                float4 o0, o1;
                o0.x = fmaxf(v[0], 0.f); o0.y = fmaxf(v[1], 0.f);
                o0.z = fmaxf(v[2], 0.f); o0.w = fmaxf(v[3], 0.f);
                o1.x = fmaxf(v[4], 0.f); o1.y = fmaxf(v[5], 0.f);
                o1.z = fmaxf(v[6], 0.f); o1.w = fmaxf(v[7], 0.f);
                *(float4*)&h1s[(r0 + r) * kPitch + c0]     = o0;
                *(float4*)&h1s[(r0 + r) * kPitch + c0 + 4] = o1;
            }
        }
        __syncthreads();

        // ---- h2 = relu(h1 @ W2 + b2) : the hot 64x128x128 GEMM (f32x2) ----
        ull acc[4][4];
        #pragma unroll
        for (int r = 0; r < 4; r++)
            #pragma unroll
            for (int j = 0; j < 4; j++) acc[r][j] = b2p[j];
        #pragma unroll 2
        for (int k = 0; k < kH; k++) {
            ull av2[4];
            #pragma unroll
            for (int r = 0; r < 4; r++)
                av2[r] = pack_dup(h1s[(r0 + r) * kPitch + k]);
            ulonglong2 wA = *(const ulonglong2*)&W2s[k * kPitch + c0];
            ulonglong2 wB = *(const ulonglong2*)&W2s[k * kPitch + c0 + 4];
            #pragma unroll
            for (int r = 0; r < 4; r++) {
                acc[r][0] = fma2(av2[r], wA.x, acc[r][0]);
                acc[r][1] = fma2(av2[r], wA.y, acc[r][1]);
                acc[r][2] = fma2(av2[r], wB.x, acc[r][2]);
                acc[r][3] = fma2(av2[r], wB.y, acc[r][3]);
            }
        }

        // ---- act = relu(h2) @ W3 + b3 ; reduce across 16 column threads ----
        float pact[4];
        #pragma unroll
        for (int r = 0; r < 4; r++) {
            float s = 0.f;
            #pragma unroll
            for (int j = 0; j < 4; j++) {
                float lo, hi;
                unpack2(acc[r][j], lo, hi);
                s = fmaf(fmaxf(lo, 0.f), w3r[2 * j], s);
                s = fmaf(fmaxf(hi, 0.f), w3r[2 * j + 1], s);
            }
            pact[r] = s;
        }
        #pragma unroll
        for (int off = 8; off >= 1; off >>= 1)
            #pragma unroll
            for (int r = 0; r < 4; r++)
                pact[r] += __shfl_xor_sync(0xFFFFFFFFu, pact[r], off, 16);
        if (tx == 0) {
            #pragma unroll
            for (int r = 0; r < 4; r++) {
                float a = pact[r] + b3v;
                acts[r0 + r] = a;
                out[(size_t)(rowBase + r0 + r) * kT + t] = a;
            }
        }
        __syncthreads();
    }
}

extern "C" void kernel_launch(void* const* d_in, const int* in_sizes, int n_in,
                              void* d_out, int out_size)
{
    (void)in_sizes; (void)n_in; (void)out_size;
    const float* proj  = (const float*)d_in[0];
    const float* idm   = (const float*)d_in[1];
    const float* merg  = (const float*)d_in[2];
    const float* W1    = (const float*)d_in[3];
    const float* b1    = (const float*)d_in[4];
    const float* W2    = (const float*)d_in[5];
    const float* b2    = (const float*)d_in[6];
    const float* W3    = (const float*)d_in[7];
    const float* b3    = (const float*)d_in[8];
    const float* smean = (const float*)d_in[9];
    const float* svar  = (const float*)d_in[10];
    float* out = (float*)d_out;

    const size_t smemBytes = (size_t)SMEM_FLOATS * sizeof(float);
    cudaFuncSetAttribute(fsim_kernel,
                         cudaFuncAttributeMaxDynamicSharedMemorySize,
                         (int)smemBytes);
    fsim_kernel<<<kB / kM, kThreads, smemBytes>>>(
        proj, idm, merg, W1, b1, W2, b2, W3, b3, smean, svar, out);
}

// round 4
// speedup vs baseline: 2.7680x; 2.7680x over previous
#include <cuda_runtime.h>
#include <cuda_fp16.h>
#include <cstddef>

// ForwardSim via mma.sync HMMA (sm_103 baseline PTX; tcgen05 is 'a'-gated and
// unavailable under the harness's .target sm_103).
// Per CTA: persistent 64-row tile, 256 thr (8 warps = 4 m-blocks x 2 col-halves).
//  - W2 split fp16 hi/lo, stored fragment-native in smem (one LDS.128 / 3 mmas).
//  - projAcc = proj@W1[:64]+b1 precomputed once into smem (permuted cols).
//  - per step: h1 computed per-thread directly in mma A-fragment layout
//    (f32x2 FMA), relu+fp16-split in regs, 192 mma.m16n8k16 per warp,
//    epilogue relu(D+b2).W3 with shfl reduce.

using u32 = unsigned int;
using u64 = unsigned long long;

namespace {
constexpr int kB = 32768, kT = 50, kH = 128, kM = 64, kThreads = 256;
constexpr int PACC_PITCH = 132;

// smem byte offsets
constexpr int OFF_BFRAG = 0;                              // 65536
constexpr int OFF_PACC  = 65536;                          // 64*132*4 = 33792
constexpr int OFF_W1EP  = OFF_PACC + 64 * PACC_PITCH * 4; // 99328, 9*128*4
constexpr int OFF_ENV   = OFF_W1EP + 9 * 128 * 4;         // 103936, 64*13*4
constexpr int OFF_BW    = OFF_ENV + 64 * 13 * 4;          // 107264, 64*16
constexpr int OFF_PART  = OFF_BW + 1024;                  // 108288, 512
constexpr int OFF_SC    = OFF_PART + 512;                 // 108800, 64
constexpr int SMEM_BYTES = OFF_SC + 64;                   // 108864
// phase-1 aliases inside BFRAG region
constexpr int OFF_W1P   = OFF_BFRAG;                      // 64*128*4 = 32768
constexpr int OFF_PROJT = OFF_BFRAG + 32768;              // 64*64*4  = 16384
} // namespace

__device__ __forceinline__ u64 pack_dup(float v) {
    u64 r; asm("mov.b64 %0, {%1, %1};" : "=l"(r) : "f"(v)); return r;
}
__device__ __forceinline__ u64 pack2(float a, float b) {
    u64 r; asm("mov.b64 %0, {%1, %2};" : "=l"(r) : "f"(a), "f"(b)); return r;
}
__device__ __forceinline__ void unpack2(u64 v, float& a, float& b) {
    asm("mov.b64 {%0, %1}, %2;" : "=f"(a), "=f"(b) : "l"(v));
}
__device__ __forceinline__ u64 fma2(u64 a, u64 b, u64 c) {
    u64 d; asm("fma.rn.f32x2 %0, %1, %2, %3;" : "=l"(d) : "l"(a), "l"(b), "l"(c));
    return d;
}

// col permutation: orig col c -> perm index so each thread's 4 A/h1 cols per
// 16-wide k-block {2q, 2q+1, 2q+8, 2q+9} become contiguous [kb*16 + q*4 .. +3]
__device__ __forceinline__ int pcol(int c) {
    return (c & ~15) | (((c >> 1) & 3) << 2) | (((c >> 3) & 1) << 1) | (c & 1);
}

__device__ __forceinline__ void split2(float f0, float f1, u32& hi, u32& lo) {
    __half h0 = __float2half_rn(f0), h1 = __float2half_rn(f1);
    __half2 hh = __halves2half2(h0, h1);          // low = h0
    hi = reinterpret_cast<u32&>(hh);
    __half2 ll = __floats2half2_rn(f0 - __half2float(h0),
                                   f1 - __half2float(h1));
    lo = reinterpret_cast<u32&>(ll);
}

__device__ __forceinline__ void relu_split(u64 h, u32& hi, u32& lo) {
    float f0, f1;
    unpack2(h, f0, f1);
    split2(fmaxf(f0, 0.f), fmaxf(f1, 0.f), hi, lo);
}

__device__ __forceinline__ void mma16816(float d[4], u32 a0, u32 a1, u32 a2,
                                         u32 a3, u32 b0, u32 b1) {
    asm volatile(
        "mma.sync.aligned.m16n8k16.row.col.f32.f16.f16.f32 "
        "{%0,%1,%2,%3}, {%4,%5,%6,%7}, {%8,%9}, {%0,%1,%2,%3};"
        : "+f"(d[0]), "+f"(d[1]), "+f"(d[2]), "+f"(d[3])
        : "r"(a0), "r"(a1), "r"(a2), "r"(a3), "r"(b0), "r"(b1));
}

__global__ void __launch_bounds__(kThreads, 2)
fsim_mma(const float* __restrict__ proj, const float* __restrict__ idm,
         const float* __restrict__ merg, const float* __restrict__ W1,
         const float* __restrict__ b1,   const float* __restrict__ W2,
         const float* __restrict__ b2,   const float* __restrict__ W3,
         const float* __restrict__ b3,   const float* __restrict__ smean,
         const float* __restrict__ svar, float* __restrict__ out)
{
    extern __shared__ char smem[];
    float* smf = (float*)smem;

    const int tid = threadIdx.x, wid = tid >> 5, lane = tid & 31;
    const int mb = wid >> 1, ch = wid & 1, g = lane >> 2, q = lane & 3;
    const int r0 = mb * 16 + g, r1 = r0 + 8;
    const int rowBase = blockIdx.x * kM;

    // ---------------- phase A: stage ----------------
    for (int i = tid; i < 64 * kH; i += kThreads) {
        int k = i >> 7, c = i & 127;
        smf[(OFF_W1P >> 2) + k * 128 + pcol(c)] = W1[i];
    }
    for (int i = tid; i < 64 * 64; i += kThreads) {
        int r = i >> 6, k = i & 63;
        smf[(OFF_PROJT >> 2) + k * 64 + r] = proj[(size_t)(rowBase + r) * 64 + k];
    }
    for (int i = tid; i < 9 * kH; i += kThreads) {
        int j = i >> 7, c = i & 127;
        smf[(OFF_W1EP >> 2) + j * 128 + pcol(c)] = W1[64 * kH + i];
    }
    if (tid < 64) {
        int c = tid * 2;
        float4 v;
        v.x = b2[c]; v.y = b2[c + 1]; v.z = W3[c]; v.w = W3[c + 1];
        *(float4*)(smem + OFF_BW + tid * 16) = v;
    }
    if (tid < 6) {
        smf[(OFF_SC >> 2) + tid]     = smean[tid];
        smf[(OFF_SC >> 2) + 8 + tid] = rsqrtf(svar[tid]);
    }
    __syncthreads();

    // ---------------- phase B: projAcc = proj@W1[:64] + b1 -> smem ---------
    {
        u64 pa0[8][2], pa1[8][2];
        #pragma unroll
        for (int kb = 0; kb < 8; kb++) {
            int cb = kb * 16 + q * 2;
            u64 blo = pack2(__ldg(&b1[cb]),     __ldg(&b1[cb + 1]));
            u64 bhi = pack2(__ldg(&b1[cb + 8]), __ldg(&b1[cb + 9]));
            pa0[kb][0] = blo; pa0[kb][1] = bhi;
            pa1[kb][0] = blo; pa1[kb][1] = bhi;
        }
        for (int k = 0; k < 64; k++) {
            u64 a0 = pack_dup(smf[(OFF_PROJT >> 2) + k * 64 + r0]);
            u64 a1 = pack_dup(smf[(OFF_PROJT >> 2) + k * 64 + r1]);
            #pragma unroll
            for (int kb = 0; kb < 8; kb++) {
                ulonglong2 w = *(const ulonglong2*)
                    &smf[(OFF_W1P >> 2) + k * 128 + kb * 16 + q * 4];
                pa0[kb][0] = fma2(a0, w.x, pa0[kb][0]);
                pa0[kb][1] = fma2(a0, w.y, pa0[kb][1]);
                pa1[kb][0] = fma2(a1, w.x, pa1[kb][0]);
                pa1[kb][1] = fma2(a1, w.y, pa1[kb][1]);
            }
        }
        #pragma unroll
        for (int kb = 0; kb < 8; kb++) {
            *(ulonglong2*)&smf[(OFF_PACC >> 2) + r0 * PACC_PITCH + kb * 16 + q * 4]
                = make_ulonglong2(pa0[kb][0], pa0[kb][1]);
            *(ulonglong2*)&smf[(OFF_PACC >> 2) + r1 * PACC_PITCH + kb * 16 + q * 4]
                = make_ulonglong2(pa1[kb][0], pa1[kb][1]);
        }
    }
    __syncthreads();

    // ---------------- phase C: W2 -> fragment-native fp16 hi/lo ------------
    // entry (c2,kb,nf,t): 16B = [b0hi, b1hi, b0lo, b1lo]
    for (int i = tid; i < 4096; i += kThreads) {
        int t  = i & 31, nf = (i >> 5) & 7, kb = (i >> 8) & 7, c2 = (i >> 11) & 1;
        int gg = t >> 2, qq = t & 3;
        int n  = c2 * 64 + nf * 8 + gg;
        int k0 = kb * 16 + qq * 2;
        float w00 = W2[(size_t)k0 * 128 + n];
        float w01 = W2[(size_t)(k0 + 1) * 128 + n];
        float w10 = W2[(size_t)(k0 + 8) * 128 + n];
        float w11 = W2[(size_t)(k0 + 9) * 128 + n];
        u32 h0, l0, h1v, l1v;
        split2(w00, w01, h0, l0);
        split2(w10, w11, h1v, l1v);
        ulonglong2 e;
        e.x = ((u64)h1v << 32) | h0;
        e.y = ((u64)l1v << 32) | l0;
        *(ulonglong2*)(smem + OFF_BFRAG +
                       (size_t)(((c2 * 8 + kb) * 8 + nf) * 32 + t) * 16) = e;
    }
    __syncthreads();

    const float b3v = __ldg(&b3[0]);
    float ego_v = 0.f, ego_x = 0.f, act_c = 0.f;   // carry lives in tid<64

    // ================= timestep loop =================
    for (int t = 0; t < kT; t++) {
        // ---- env features (one thread per row) ----
        if (tid < kM) {
            const float* sp = idm + (size_t)(rowBase + tid) * (kT * 12) + t * 12;
            float4 a0 = *(const float4*)sp;
            float4 a1 = *(const float4*)(sp + 4);
            float s11 = sp[11];
            if (t == 0) { ego_v = a0.x; ego_x = a0.w; }
            else {
                ego_v = fmaf(act_c, 0.1f, ego_v);
                ego_x = ego_x + ego_v * 0.1f + act_c * 0.005f;
            }
            float ev[6];
            ev[0] = ego_v;
            ev[1] = a0.y;
            ev[2] = ego_v - a0.y;
            ev[3] = a1.x - ego_x;
            ev[4] = (ego_v - a0.z) * s11;
            ev[5] = (a1.y - ego_x) * s11 + (1.0f - s11) * 100.0f;
            #pragma unroll
            for (int j = 0; j < 6; j++)
                smf[(OFF_ENV >> 2) + tid * 13 + j] =
                    (ev[j] - smf[(OFF_SC >> 2) + j]) * smf[(OFF_SC >> 2) + 8 + j];
            const float* mp = merg + (size_t)(rowBase + tid) * (kT * 3) + t * 3;
            smf[(OFF_ENV >> 2) + tid * 13 + 6] = mp[0];
            smf[(OFF_ENV >> 2) + tid * 13 + 7] = mp[1];
            smf[(OFF_ENV >> 2) + tid * 13 + 8] = mp[2];
        }
        __syncthreads();

        float e0[9], e1[9];
        #pragma unroll
        for (int j = 0; j < 9; j++) {
            e0[j] = smf[(OFF_ENV >> 2) + r0 * 13 + j];
            e1[j] = smf[(OFF_ENV >> 2) + r1 * 13 + j];
        }

        float d[8][4];
        #pragma unroll
        for (int nf = 0; nf < 8; nf++)
            d[nf][0] = d[nf][1] = d[nf][2] = d[nf][3] = 0.f;

        #pragma unroll
        for (int kb = 0; kb < 8; kb++) {
            // h1 fragment for this k-block (A rows g, g+8; cols 2q,2q+1,+8,+9)
            ulonglong2 p0 = *(const ulonglong2*)
                &smf[(OFF_PACC >> 2) + r0 * PACC_PITCH + kb * 16 + q * 4];
            ulonglong2 p1 = *(const ulonglong2*)
                &smf[(OFF_PACC >> 2) + r1 * PACC_PITCH + kb * 16 + q * 4];
            u64 hA = p0.x, hC = p0.y, hB = p1.x, hD = p1.y;
            #pragma unroll
            for (int j = 0; j < 9; j++) {
                ulonglong2 w = *(const ulonglong2*)
                    &smf[(OFF_W1EP >> 2) + j * 128 + kb * 16 + q * 4];
                u64 m0 = pack_dup(e0[j]), m1 = pack_dup(e1[j]);
                hA = fma2(m0, w.x, hA);
                hC = fma2(m0, w.y, hC);
                hB = fma2(m1, w.x, hB);
                hD = fma2(m1, w.y, hD);
            }
            u32 a0, a1, a2, a3, l0, l1, l2, l3;
            relu_split(hA, a0, l0);
            relu_split(hB, a1, l1);
            relu_split(hC, a2, l2);
            relu_split(hD, a3, l3);

            const char* bfp = smem + OFF_BFRAG +
                              (size_t)((ch * 8 + kb) * 8) * 512 + lane * 16;
            #pragma unroll
            for (int nf = 0; nf < 8; nf++) {
                ulonglong2 bf = *(const ulonglong2*)(bfp + nf * 512);
                u32 bh0 = (u32)bf.x, bh1 = (u32)(bf.x >> 32);
                u32 bl0 = (u32)bf.y, bl1 = (u32)(bf.y >> 32);
                mma16816(d[nf], a0, a1, a2, a3, bh0, bh1);  // hi*hi
                mma16816(d[nf], l0, l1, l2, l3, bh0, bh1);  // lo*hi
                mma16816(d[nf], a0, a1, a2, a3, bl0, bl1);  // hi*lo
            }
        }

        // ---- epilogue: relu(D + b2) . W3 ----
        float s0 = 0.f, s1 = 0.f;
        #pragma unroll
        for (int nf = 0; nf < 8; nf++) {
            float4 bw = *(const float4*)(smem + OFF_BW +
                                         (ch * 32 + nf * 4 + q) * 16);
            s0 += fmaxf(d[nf][0] + bw.x, 0.f) * bw.z +
                  fmaxf(d[nf][1] + bw.y, 0.f) * bw.w;
            s1 += fmaxf(d[nf][2] + bw.x, 0.f) * bw.z +
                  fmaxf(d[nf][3] + bw.y, 0.f) * bw.w;
        }
        s0 += __shfl_xor_sync(0xFFFFFFFFu, s0, 1);
        s0 += __shfl_xor_sync(0xFFFFFFFFu, s0, 2);
        s1 += __shfl_xor_sync(0xFFFFFFFFu, s1, 1);
        s1 += __shfl_xor_sync(0xFFFFFFFFu, s1, 2);
        if (q == 0) {
            smf[(OFF_PART >> 2) + ch * 64 + r0] = s0;
            smf[(OFF_PART >> 2) + ch * 64 + r1] = s1;
        }
        __syncthreads();

        if (tid < kM) {
            float a = smf[(OFF_PART >> 2) + tid] +
                      smf[(OFF_PART >> 2) + 64 + tid] + b3v;
            act_c = a;
            out[(size_t)(rowBase + tid) * kT + t] = a;
        }
        // next-iter env write (tid<64) is ordered behind this sync pair; all
        // other warps re-block at the next syncthreads before touching env.
    }
}

extern "C" void kernel_launch(void* const* d_in, const int* in_sizes, int n_in,
                              void* d_out, int out_size)
{
    (void)in_sizes; (void)n_in; (void)out_size;
    const float* proj  = (const float*)d_in[0];
    const float* idm   = (const float*)d_in[1];
    const float* merg  = (const float*)d_in[2];
    const float* W1    = (const float*)d_in[3];
    const float* b1    = (const float*)d_in[4];
    const float* W2    = (const float*)d_in[5];
    const float* b2    = (const float*)d_in[6];
    const float* W3    = (const float*)d_in[7];
    const float* b3    = (const float*)d_in[8];
    const float* smean = (const float*)d_in[9];
    const float* svar  = (const float*)d_in[10];
    float* out = (float*)d_out;

    cudaFuncSetAttribute(fsim_mma, cudaFuncAttributeMaxDynamicSharedMemorySize,
                         SMEM_BYTES);
    fsim_mma<<<kB / kM, kThreads, SMEM_BYTES>>>(
        proj, idm, merg, W1, b1, W2, b2, W3, b3, smean, svar, out);
}